// round 1
// baseline (speedup 1.0000x reference)
#include <cuda_runtime.h>
#include <math.h>

#define NN 10000
#define EE 160000
#define HH 4

// ---------------- static scratch (no allocation allowed) ----------------
__device__ float g_feat[NN * 1024];   // [N, H*Dmax] Dmax=256
__device__ float g_res [NN * 256];    // [N, Dmax]
__device__ float g_hA  [NN * 128];
__device__ float g_hB  [NN * 128];
__device__ float g_el  [NN * HH];
__device__ float g_er  [NN * HH];
__device__ float g_alpha[EE * HH];    // CSR-ordered
__device__ float g_eedge[EE * HH];    // original-edge-ordered (layer 1 only)
__device__ int   g_off [NN + 1];
__device__ int   g_cur [NN];
__device__ int   g_csrc[EE];
__device__ int   g_ceid[EE];
__device__ float g_alv [128 * HH];
__device__ float g_arv [128 * HH];
__device__ float g_wev [64 * HH];

// ---------------- packed f32x2 FMA (2x fp32 FMA throughput on sm_103a) ----
__device__ __forceinline__ void ffma2(float2& c, float a, float2 b) {
    float2 a2 = make_float2(a, a);
    unsigned long long aa = *reinterpret_cast<unsigned long long*>(&a2);
    unsigned long long bb = *reinterpret_cast<unsigned long long*>(&b);
    unsigned long long cc = *reinterpret_cast<unsigned long long*>(&c);
    asm("fma.rn.f32x2 %0, %1, %2, %0;" : "+l"(cc) : "l"(aa), "l"(bb));
    c = *reinterpret_cast<float2*>(&cc);
}

// ---------------- SGEMM: C[M,Nc] = A[M,128] @ B[128,Nc] --------------------
// BM=64, BN=64, BK=16, 256 threads, 4x4 per-thread tile, f32x2 accumulators.
__global__ void sgemm128(const float* __restrict__ A, const float* __restrict__ B,
                         float* __restrict__ C, int M, int Nc) {
    __shared__ float As[16][64];   // [k][m] (A transposed at load)
    __shared__ float Bs[16][64];   // [k][n]
    int tid = threadIdx.x;
    int tx = tid & 15, ty = tid >> 4;
    int rowBase = blockIdx.x * 64;
    int colBase = blockIdx.y * 64;

    float2 acc[4][2];
#pragma unroll
    for (int i = 0; i < 4; i++) { acc[i][0] = make_float2(0.f, 0.f); acc[i][1] = make_float2(0.f, 0.f); }

    int ra = tid >> 2, kq = tid & 3;       // A-tile load mapping
    int kr = tid >> 4, cb = (tid & 15) << 2; // B-tile load mapping

    for (int k0 = 0; k0 < 128; k0 += 16) {
        float4 av = make_float4(0.f, 0.f, 0.f, 0.f);
        if (rowBase + ra < M)
            av = *(const float4*)(A + (size_t)(rowBase + ra) * 128 + k0 + kq * 4);
        As[kq * 4 + 0][ra] = av.x;
        As[kq * 4 + 1][ra] = av.y;
        As[kq * 4 + 2][ra] = av.z;
        As[kq * 4 + 3][ra] = av.w;
        *(float4*)(&Bs[kr][cb]) = *(const float4*)(B + (size_t)(k0 + kr) * Nc + colBase + cb);
        __syncthreads();
#pragma unroll
        for (int k = 0; k < 16; k++) {
            float4 a4 = *(float4*)(&As[k][ty * 4]);
            float4 b4 = *(float4*)(&Bs[k][tx * 4]);
            float2 b01 = make_float2(b4.x, b4.y);
            float2 b23 = make_float2(b4.z, b4.w);
            ffma2(acc[0][0], a4.x, b01); ffma2(acc[0][1], a4.x, b23);
            ffma2(acc[1][0], a4.y, b01); ffma2(acc[1][1], a4.y, b23);
            ffma2(acc[2][0], a4.z, b01); ffma2(acc[2][1], a4.z, b23);
            ffma2(acc[3][0], a4.w, b01); ffma2(acc[3][1], a4.w, b23);
        }
        __syncthreads();
    }
#pragma unroll
    for (int i = 0; i < 4; i++) {
        int row = rowBase + ty * 4 + i;
        if (row < M) {
            float4 o = make_float4(acc[i][0].x, acc[i][0].y, acc[i][1].x, acc[i][1].y);
            *(float4*)(C + (size_t)row * Nc + colBase + tx * 4) = o;
        }
    }
}

// ---------------- contract W[Fin,H,D] with vec[H,D] -> out[Fin,H] ----------
__global__ void contract_kernel(const float* __restrict__ W,
                                const float* __restrict__ vl, const float* __restrict__ vr,
                                float* __restrict__ outL, float* __restrict__ outR,
                                int Fin, int D) {
    int t = blockIdx.x * blockDim.x + threadIdx.x;
    if (t >= Fin * HH) return;
    int i = t >> 2, h = t & 3;
    const float* wr = W + (size_t)(i * HH + h) * D;
    const float* al = vl + h * D;
    float sl = 0.f;
    for (int d = 0; d < D; d++) sl = fmaf(wr[d], al[d], sl);
    outL[t] = sl;
    if (outR) {
        const float* arp = vr + h * D;
        float sr = 0.f;
        for (int d = 0; d < D; d++) sr = fmaf(wr[d], arp[d], sr);
        outR[t] = sr;
    }
}

// ---------------- el/er per node: x[n,:] . alv/arv -------------------------
__global__ void eler_kernel(const float* __restrict__ x) {
    int t = blockIdx.x * blockDim.x + threadIdx.x;
    if (t >= NN * HH) return;
    int n = t >> 2, h = t & 3;
    const float* xr = x + (size_t)n * 128;
    float l = 0.f, r = 0.f;
#pragma unroll 8
    for (int i = 0; i < 128; i++) {
        float xv = xr[i];
        l = fmaf(xv, g_alv[i * 4 + h], l);
        r = fmaf(xv, g_arv[i * 4 + h], r);
    }
    g_el[t] = l;
    g_er[t] = r;
}

// ---------------- edge term (layer 1): edge_feats[E,64] @ wev[64,4] --------
__global__ void eedge_kernel(const float* __restrict__ ef) {
    int warp = (blockIdx.x * blockDim.x + threadIdx.x) >> 5;
    int lane = threadIdx.x & 31;
    if (warp >= EE) return;
    const float* row = ef + (size_t)warp * 64;
    float e0 = row[lane], e1 = row[lane + 32];
    float p[4];
#pragma unroll
    for (int h = 0; h < 4; h++)
        p[h] = e0 * g_wev[lane * 4 + h] + e1 * g_wev[(lane + 32) * 4 + h];
#pragma unroll
    for (int off = 16; off; off >>= 1) {
#pragma unroll
        for (int h = 0; h < 4; h++) p[h] += __shfl_xor_sync(0xffffffffu, p[h], off);
    }
    if (lane == 0) {
        float4 o = make_float4(p[0], p[1], p[2], p[3]);
        *(float4*)(g_eedge + (size_t)warp * 4) = o;
    }
}

// ---------------- CSR build -------------------------------------------------
__global__ void zero_cur() {
    int i = blockIdx.x * blockDim.x + threadIdx.x;
    if (i < NN) g_cur[i] = 0;
}
__global__ void count_kernel(const int* __restrict__ dst) {
    int e = blockIdx.x * blockDim.x + threadIdx.x;
    if (e < EE) atomicAdd(&g_cur[dst[e]], 1);
}
__global__ void scan_kernel() {
    __shared__ int sh[1024];
    int t = threadIdx.x;
    int vals[10];
    int base = t * 10;
    int s = 0;
#pragma unroll
    for (int j = 0; j < 10; j++) {
        int idx = base + j;
        int v = (idx < NN) ? g_cur[idx] : 0;
        vals[j] = s;
        s += v;
    }
    sh[t] = s;
    __syncthreads();
    for (int off = 1; off < 1024; off <<= 1) {
        int v = (t >= off) ? sh[t - off] : 0;
        __syncthreads();
        sh[t] += v;
        __syncthreads();
    }
    int excl = (t > 0) ? sh[t - 1] : 0;
#pragma unroll
    for (int j = 0; j < 10; j++) {
        int idx = base + j;
        if (idx < NN) {
            int o = excl + vals[j];
            g_off[idx] = o;
            g_cur[idx] = o;   // cursor for scatter
        }
    }
    if (t == 1023) g_off[NN] = sh[1023];
}
__global__ void scatter_kernel(const int* __restrict__ src, const int* __restrict__ dst) {
    int e = blockIdx.x * blockDim.x + threadIdx.x;
    if (e < EE) {
        int p = atomicAdd(&g_cur[dst[e]], 1);
        g_csrc[p] = src[e];
        g_ceid[p] = e;
    }
}

// ---------------- edge softmax (warp per dst node) --------------------------
__global__ void alpha_kernel(int use_edge) {
    int warp = (blockIdx.x * blockDim.x + threadIdx.x) >> 5;
    int lane = threadIdx.x & 31;
    if (warp >= NN) return;
    int n = warp;
    int b = g_off[n];
    int deg4 = (g_off[n + 1] - b) * 4;
    int h = lane & 3;   // h is invariant under t += 32
    float ern = g_er[n * 4 + h];

    float mx = -1e30f;
    for (int t = lane; t < deg4; t += 32) {
        int p = b + (t >> 2);
        float e = g_el[g_csrc[p] * 4 + h] + ern;
        if (use_edge) e += g_eedge[(size_t)g_ceid[p] * 4 + h];
        e = e > 0.f ? e : 0.2f * e;
        mx = fmaxf(mx, e);
    }
    mx = fmaxf(mx, __shfl_xor_sync(0xffffffffu, mx, 4));
    mx = fmaxf(mx, __shfl_xor_sync(0xffffffffu, mx, 8));
    mx = fmaxf(mx, __shfl_xor_sync(0xffffffffu, mx, 16));

    float sum = 0.f;
    for (int t = lane; t < deg4; t += 32) {
        int p = b + (t >> 2);
        float e = g_el[g_csrc[p] * 4 + h] + ern;
        if (use_edge) e += g_eedge[(size_t)g_ceid[p] * 4 + h];
        e = e > 0.f ? e : 0.2f * e;
        float ex = expf(e - mx);
        g_alpha[(size_t)p * 4 + h] = ex;
        sum += ex;
    }
    sum += __shfl_xor_sync(0xffffffffu, sum, 4);
    sum += __shfl_xor_sync(0xffffffffu, sum, 8);
    sum += __shfl_xor_sync(0xffffffffu, sum, 16);
    float inv = 1.f / (sum + 1e-9f);
    for (int t = lane; t < deg4; t += 32) {
        int p = b + (t >> 2);
        g_alpha[(size_t)p * 4 + h] *= inv;
    }
}

// ---------------- aggregation: block per dst node ---------------------------
template <int D>
__global__ void agg_kernel(const float* __restrict__ feat, const float* __restrict__ res,
                           float* __restrict__ out) {
    int n = blockIdx.x;
    int d = threadIdx.x;
    int b = g_off[n], e = g_off[n + 1];
    float acc = 0.f;
    for (int p = b; p < e; ++p) {
        int s = g_csrc[p];
        float4 a = *(const float4*)(g_alpha + (size_t)p * 4);
        const float* f = feat + (size_t)s * (4 * D) + d;
        acc = fmaf(a.x, f[0],     acc);
        acc = fmaf(a.y, f[D],     acc);
        acc = fmaf(a.z, f[2 * D], acc);
        acc = fmaf(a.w, f[3 * D], acc);
    }
    float v = acc * 0.25f + res[(size_t)n * D + d];
    out[(size_t)n * D + d] = v > 0.f ? v : 0.f;
}

// ---------------- host orchestration ----------------------------------------
extern "C" void kernel_launch(void* const* d_in, const int* in_sizes, int n_in,
                              void* d_out, int out_size) {
    const float* x0  = (const float*)d_in[0];
    const float* ef  = (const float*)d_in[1];
    const int*   src = (const int*)d_in[2];
    const int*   dst = (const int*)d_in[3];
    const float* W[4]   = {(const float*)d_in[4],  (const float*)d_in[10],
                           (const float*)d_in[14], (const float*)d_in[18]};
    const float* We1    = (const float*)d_in[5];
    const float* al[4]  = {(const float*)d_in[6],  (const float*)d_in[11],
                           (const float*)d_in[15], (const float*)d_in[19]};
    const float* ar[4]  = {(const float*)d_in[7],  (const float*)d_in[12],
                           (const float*)d_in[16], (const float*)d_in[20]};
    const float* ae1    = (const float*)d_in[8];
    const float* res[4] = {(const float*)d_in[9],  (const float*)d_in[13],
                           (const float*)d_in[17], (const float*)d_in[21]};

    float *p_feat, *p_res, *p_hA, *p_hB, *p_alv, *p_arv, *p_wev;
    cudaGetSymbolAddress((void**)&p_feat, g_feat);
    cudaGetSymbolAddress((void**)&p_res,  g_res);
    cudaGetSymbolAddress((void**)&p_hA,   g_hA);
    cudaGetSymbolAddress((void**)&p_hB,   g_hB);
    cudaGetSymbolAddress((void**)&p_alv,  g_alv);
    cudaGetSymbolAddress((void**)&p_arv,  g_arv);
    cudaGetSymbolAddress((void**)&p_wev,  g_wev);

    // CSR by dst (once per launch; deterministic up to fp-sum order)
    zero_cur<<<(NN + 255) / 256, 256>>>();
    count_kernel<<<(EE + 255) / 256, 256>>>(dst);
    scan_kernel<<<1, 1024>>>();
    scatter_kernel<<<(EE + 255) / 256, 256>>>(src, dst);

    const float* hin = x0;
    float* houts[4] = {p_hA, p_hB, p_hA, (float*)d_out};
    int Dl[4] = {128, 128, 128, 256};

    for (int L = 0; L < 4; L++) {
        int D = Dl[L];
        contract_kernel<<<2, 256>>>(W[L], al[L], ar[L], p_alv, p_arv, 128, D);
        if (L == 0) {
            contract_kernel<<<1, 256>>>(We1, ae1, nullptr, p_wev, nullptr, 64, 128);
            eedge_kernel<<<(EE * 32 + 255) / 256, 256>>>(ef);
        }
        dim3 g1((NN + 63) / 64, (4 * D) / 64);
        sgemm128<<<g1, 256>>>(hin, W[L], p_feat, NN, 4 * D);
        dim3 g2((NN + 63) / 64, D / 64);
        sgemm128<<<g2, 256>>>(hin, res[L], p_res, NN, D);
        eler_kernel<<<(NN * 4 + 255) / 256, 256>>>(hin);
        alpha_kernel<<<(NN * 32 + 255) / 256, 256>>>(L == 0 ? 1 : 0);
        if (D == 128) agg_kernel<128><<<NN, 128>>>(p_feat, p_res, houts[L]);
        else          agg_kernel<256><<<NN, 256>>>(p_feat, p_res, houts[L]);
        hin = houts[L];
    }
}

// round 2
// speedup vs baseline: 1.0994x; 1.0994x over previous
#include <cuda_runtime.h>
#include <math.h>

#define NN 10000
#define EE 160000
#define HH 4
#define MPAD 10112   // 79 * 128

// ---------------- static scratch ----------------
__device__ float g_feat[NN * 1024];
__device__ float g_res [NN * 256];
__device__ float g_hA  [NN * 128];
__device__ float g_hB  [NN * 128];
__device__ float g_AT  [128 * MPAD];
__device__ float g_el  [NN * HH];
__device__ float g_er  [NN * HH];
__device__ float g_inv [NN * HH];
__device__ float g_alpha[EE * HH];
__device__ float g_eedge[EE * HH];
__device__ int   g_off [NN + 1];
__device__ int   g_cur [NN];
__device__ int   g_csrc[EE];
__device__ int   g_ceid[EE];
__device__ float g_alv [128 * HH];
__device__ float g_arv [128 * HH];
__device__ float g_wev [64 * HH];

// ---------------- packed f32x2 FMA ----------------
__device__ __forceinline__ void ffma2(float2& c, float a, float2 b) {
    float2 a2 = make_float2(a, a);
    unsigned long long aa = *reinterpret_cast<unsigned long long*>(&a2);
    unsigned long long bb = *reinterpret_cast<unsigned long long*>(&b);
    unsigned long long cc = *reinterpret_cast<unsigned long long*>(&c);
    asm("fma.rn.f32x2 %0, %1, %2, %0;" : "+l"(cc) : "l"(aa), "l"(bb));
    c = *reinterpret_cast<float2*>(&cc);
}

__device__ __forceinline__ unsigned smem_u32(const void* p) {
    return (unsigned)__cvta_generic_to_shared(p);
}
__device__ __forceinline__ void cpa16(unsigned s, const float* g) {
    asm volatile("cp.async.cg.shared.global [%0], [%1], 16;" :: "r"(s), "l"(g));
}

// ---------------- transpose x[M,128] -> AT[128,MPAD] (zero padded) ----------
__global__ void transpose_kernel(const float* __restrict__ x, float* __restrict__ AT, int M) {
    __shared__ float t[32][33];
    int mBase = blockIdx.x * 32;
    int kBase = blockIdx.y * 32;
    int lx = threadIdx.x, ly = threadIdx.y;
#pragma unroll
    for (int j = 0; j < 32; j += 8) {
        int m = mBase + ly + j;
        t[ly + j][lx] = (m < M) ? x[(size_t)m * 128 + kBase + lx] : 0.f;
    }
    __syncthreads();
#pragma unroll
    for (int j = 0; j < 32; j += 8)
        AT[(size_t)(kBase + ly + j) * MPAD + mBase + lx] = t[lx][ly + j];
}

// ---------------- SGEMM: C[M,Nc] = A[M,128] @ B[128,Nc], A given transposed --
// BM=128, BN=64, BK=16, 256 threads, 8x4 thread tile, f32x2, cp.async 2-stage.
__global__ void __launch_bounds__(256) sgemm_tc(const float* __restrict__ AT,
                                                const float* __restrict__ B,
                                                float* __restrict__ C, int M, int Nc) {
    __shared__ float As[2][16][128];
    __shared__ float Bs[2][16][64];
    int tid = threadIdx.x;
    int tx = tid & 15, ty = tid >> 4;
    int rowBase = blockIdx.x * 128;
    int colBase = blockIdx.y * 64;

    float2 acc[8][2];
#pragma unroll
    for (int i = 0; i < 8; i++) { acc[i][0] = make_float2(0.f, 0.f); acc[i][1] = make_float2(0.f, 0.f); }

    // load index mappings
    int ka0 = tid >> 5,        ma0 = (tid & 31) * 4;          // A: 2 float4/thread
    int ka1 = (tid + 256) >> 5, ma1 = ((tid + 256) & 31) * 4;
    int kb_ = tid >> 4,        nb_ = (tid & 15) * 4;          // B: 1 float4/thread

    // prologue: stage 0
    cpa16(smem_u32(&As[0][ka0][ma0]), AT + (size_t)ka0 * MPAD + rowBase + ma0);
    cpa16(smem_u32(&As[0][ka1][ma1]), AT + (size_t)ka1 * MPAD + rowBase + ma1);
    cpa16(smem_u32(&Bs[0][kb_][nb_]), B + (size_t)kb_ * Nc + colBase + nb_);
    asm volatile("cp.async.commit_group;" ::: "memory");

    for (int kb = 0; kb < 8; kb++) {
        int cur = kb & 1;
        asm volatile("cp.async.wait_group 0;" ::: "memory");
        __syncthreads();
        if (kb < 7) {
            int k0 = (kb + 1) * 16;
            cpa16(smem_u32(&As[cur ^ 1][ka0][ma0]), AT + (size_t)(k0 + ka0) * MPAD + rowBase + ma0);
            cpa16(smem_u32(&As[cur ^ 1][ka1][ma1]), AT + (size_t)(k0 + ka1) * MPAD + rowBase + ma1);
            cpa16(smem_u32(&Bs[cur ^ 1][kb_][nb_]), B + (size_t)(k0 + kb_) * Nc + colBase + nb_);
            asm volatile("cp.async.commit_group;" ::: "memory");
        }
#pragma unroll
        for (int k = 0; k < 16; k++) {
            float4 a0 = *(const float4*)&As[cur][k][ty * 8];
            float4 a1 = *(const float4*)&As[cur][k][ty * 8 + 4];
            float4 b  = *(const float4*)&Bs[cur][k][tx * 4];
            float2 b01 = make_float2(b.x, b.y);
            float2 b23 = make_float2(b.z, b.w);
            ffma2(acc[0][0], a0.x, b01); ffma2(acc[0][1], a0.x, b23);
            ffma2(acc[1][0], a0.y, b01); ffma2(acc[1][1], a0.y, b23);
            ffma2(acc[2][0], a0.z, b01); ffma2(acc[2][1], a0.z, b23);
            ffma2(acc[3][0], a0.w, b01); ffma2(acc[3][1], a0.w, b23);
            ffma2(acc[4][0], a1.x, b01); ffma2(acc[4][1], a1.x, b23);
            ffma2(acc[5][0], a1.y, b01); ffma2(acc[5][1], a1.y, b23);
            ffma2(acc[6][0], a1.z, b01); ffma2(acc[6][1], a1.z, b23);
            ffma2(acc[7][0], a1.w, b01); ffma2(acc[7][1], a1.w, b23);
        }
    }
#pragma unroll
    for (int i = 0; i < 8; i++) {
        int row = rowBase + ty * 8 + i;
        if (row < M) {
            float4 o = make_float4(acc[i][0].x, acc[i][0].y, acc[i][1].x, acc[i][1].y);
            *(float4*)(C + (size_t)row * Nc + colBase + tx * 4) = o;
        }
    }
}

// ---------------- contract W[Fin,H,D] with vec[H,D] -> out[Fin,H] ----------
__global__ void contract_kernel(const float* __restrict__ W,
                                const float* __restrict__ vl, const float* __restrict__ vr,
                                float* __restrict__ outL, float* __restrict__ outR,
                                int Fin, int D) {
    int t = blockIdx.x * blockDim.x + threadIdx.x;
    if (t >= Fin * HH) return;
    int i = t >> 2, h = t & 3;
    const float* wr = W + (size_t)(i * HH + h) * D;
    const float* al = vl + h * D;
    float sl = 0.f;
    for (int d = 0; d < D; d++) sl = fmaf(wr[d], al[d], sl);
    outL[t] = sl;
    if (outR) {
        const float* arp = vr + h * D;
        float sr = 0.f;
        for (int d = 0; d < D; d++) sr = fmaf(wr[d], arp[d], sr);
        outR[t] = sr;
    }
}

// ---------------- el/er per node ----------------
__global__ void eler_kernel(const float* __restrict__ x) {
    int t = blockIdx.x * blockDim.x + threadIdx.x;
    if (t >= NN * HH) return;
    int n = t >> 2, h = t & 3;
    const float* xr = x + (size_t)n * 128;
    float l = 0.f, r = 0.f;
#pragma unroll 8
    for (int i = 0; i < 128; i++) {
        float xv = xr[i];
        l = fmaf(xv, g_alv[i * 4 + h], l);
        r = fmaf(xv, g_arv[i * 4 + h], r);
    }
    g_el[t] = l;
    g_er[t] = r;
}

// ---------------- edge logit term (layer 1 only) ----------------
__global__ void eedge_kernel(const float* __restrict__ ef) {
    int warp = (blockIdx.x * blockDim.x + threadIdx.x) >> 5;
    int lane = threadIdx.x & 31;
    if (warp >= EE) return;
    const float* row = ef + (size_t)warp * 64;
    float e0 = row[lane], e1 = row[lane + 32];
    float p[4];
#pragma unroll
    for (int h = 0; h < 4; h++)
        p[h] = e0 * g_wev[lane * 4 + h] + e1 * g_wev[(lane + 32) * 4 + h];
#pragma unroll
    for (int off = 16; off; off >>= 1) {
#pragma unroll
        for (int h = 0; h < 4; h++) p[h] += __shfl_xor_sync(0xffffffffu, p[h], off);
    }
    if (lane == 0) {
        float4 o = make_float4(p[0], p[1], p[2], p[3]);
        *(float4*)(g_eedge + (size_t)warp * 4) = o;
    }
}

// ---------------- CSR build ----------------
__global__ void zero_cur() {
    int i = blockIdx.x * blockDim.x + threadIdx.x;
    if (i < NN) g_cur[i] = 0;
}
__global__ void count_kernel(const int* __restrict__ dst) {
    int e = blockIdx.x * blockDim.x + threadIdx.x;
    if (e < EE) atomicAdd(&g_cur[dst[e]], 1);
}
__global__ void scan_kernel() {
    __shared__ int sh[1024];
    int t = threadIdx.x;
    int vals[10];
    int base = t * 10;
    int s = 0;
#pragma unroll
    for (int j = 0; j < 10; j++) {
        int idx = base + j;
        int v = (idx < NN) ? g_cur[idx] : 0;
        vals[j] = s;
        s += v;
    }
    sh[t] = s;
    __syncthreads();
    for (int off = 1; off < 1024; off <<= 1) {
        int v = (t >= off) ? sh[t - off] : 0;
        __syncthreads();
        sh[t] += v;
        __syncthreads();
    }
    int excl = (t > 0) ? sh[t - 1] : 0;
#pragma unroll
    for (int j = 0; j < 10; j++) {
        int idx = base + j;
        if (idx < NN) {
            int o = excl + vals[j];
            g_off[idx] = o;
            g_cur[idx] = o;
        }
    }
    if (t == 1023) g_off[NN] = sh[1023];
}
__global__ void scatter_kernel(const int* __restrict__ src, const int* __restrict__ dst) {
    int e = blockIdx.x * blockDim.x + threadIdx.x;
    if (e < EE) {
        int p = atomicAdd(&g_cur[dst[e]], 1);
        g_csrc[p] = src[e];
        g_ceid[p] = e;
    }
}

// ---------------- edge softmax: unnormalized exp + per-(n,h) inverse --------
__global__ void alpha_kernel(int use_edge) {
    int warp = (blockIdx.x * blockDim.x + threadIdx.x) >> 5;
    int lane = threadIdx.x & 31;
    if (warp >= NN) return;
    int n = warp;
    int b = g_off[n];
    int deg4 = (g_off[n + 1] - b) * 4;
    int h = lane & 3;
    float ern = g_er[n * 4 + h];

    float mx = -1e30f;
    for (int t = lane; t < deg4; t += 32) {
        int p = b + (t >> 2);
        float e = g_el[g_csrc[p] * 4 + h] + ern;
        if (use_edge) e += g_eedge[(size_t)g_ceid[p] * 4 + h];
        e = e > 0.f ? e : 0.2f * e;
        mx = fmaxf(mx, e);
    }
    mx = fmaxf(mx, __shfl_xor_sync(0xffffffffu, mx, 4));
    mx = fmaxf(mx, __shfl_xor_sync(0xffffffffu, mx, 8));
    mx = fmaxf(mx, __shfl_xor_sync(0xffffffffu, mx, 16));

    float sum = 0.f;
    for (int t = lane; t < deg4; t += 32) {
        int p = b + (t >> 2);
        float e = g_el[g_csrc[p] * 4 + h] + ern;
        if (use_edge) e += g_eedge[(size_t)g_ceid[p] * 4 + h];
        e = e > 0.f ? e : 0.2f * e;
        float ex = expf(e - mx);
        g_alpha[(size_t)p * 4 + h] = ex;
        sum += ex;
    }
    sum += __shfl_xor_sync(0xffffffffu, sum, 4);
    sum += __shfl_xor_sync(0xffffffffu, sum, 8);
    sum += __shfl_xor_sync(0xffffffffu, sum, 16);
    if (lane < 4) g_inv[n * 4 + h] = 1.f / (sum + 1e-9f);
}

// ---------------- aggregation: float4 gathers, smem cross-head reduce -------
template <int D>
__global__ void agg_kernel(const float* __restrict__ feat, const float* __restrict__ res,
                           float* __restrict__ out) {
    constexpr int DG = D / 4;
    int n = blockIdx.x;
    int tid = threadIdx.x;            // 4*DG threads
    int h = tid / DG;
    int dg = tid % DG;
    int b = g_off[n], e = g_off[n + 1];
    float4 acc = make_float4(0.f, 0.f, 0.f, 0.f);
    const float* fbase = feat + h * D + dg * 4;
    for (int p = b; p < e; ++p) {
        int s = g_csrc[p];
        float a = g_alpha[(size_t)p * 4 + h];
        float4 f = *(const float4*)(fbase + (size_t)s * (4 * D));
        acc.x = fmaf(a, f.x, acc.x);
        acc.y = fmaf(a, f.y, acc.y);
        acc.z = fmaf(a, f.z, acc.z);
        acc.w = fmaf(a, f.w, acc.w);
    }
    float sc = g_inv[n * 4 + h] * 0.25f;
    acc.x *= sc; acc.y *= sc; acc.z *= sc; acc.w *= sc;

    __shared__ float4 sh[4 * DG];
    sh[tid] = acc;
    __syncthreads();
    if (tid < DG) {
        float4 r0 = sh[tid], r1 = sh[DG + tid], r2 = sh[2 * DG + tid], r3 = sh[3 * DG + tid];
        float4 rr = *(const float4*)(res + (size_t)n * D + tid * 4);
        float4 o;
        o.x = fmaxf(r0.x + r1.x + r2.x + r3.x + rr.x, 0.f);
        o.y = fmaxf(r0.y + r1.y + r2.y + r3.y + rr.y, 0.f);
        o.z = fmaxf(r0.z + r1.z + r2.z + r3.z + rr.z, 0.f);
        o.w = fmaxf(r0.w + r1.w + r2.w + r3.w + rr.w, 0.f);
        *(float4*)(out + (size_t)n * D + tid * 4) = o;
    }
}

// ---------------- host orchestration ----------------
extern "C" void kernel_launch(void* const* d_in, const int* in_sizes, int n_in,
                              void* d_out, int out_size) {
    const float* x0  = (const float*)d_in[0];
    const float* ef  = (const float*)d_in[1];
    const int*   src = (const int*)d_in[2];
    const int*   dst = (const int*)d_in[3];
    const float* W[4]   = {(const float*)d_in[4],  (const float*)d_in[10],
                           (const float*)d_in[14], (const float*)d_in[18]};
    const float* We1    = (const float*)d_in[5];
    const float* al[4]  = {(const float*)d_in[6],  (const float*)d_in[11],
                           (const float*)d_in[15], (const float*)d_in[19]};
    const float* ar[4]  = {(const float*)d_in[7],  (const float*)d_in[12],
                           (const float*)d_in[16], (const float*)d_in[20]};
    const float* ae1    = (const float*)d_in[8];
    const float* res[4] = {(const float*)d_in[9],  (const float*)d_in[13],
                           (const float*)d_in[17], (const float*)d_in[21]};

    float *p_feat, *p_res, *p_hA, *p_hB, *p_alv, *p_arv, *p_wev, *p_AT;
    cudaGetSymbolAddress((void**)&p_feat, g_feat);
    cudaGetSymbolAddress((void**)&p_res,  g_res);
    cudaGetSymbolAddress((void**)&p_hA,   g_hA);
    cudaGetSymbolAddress((void**)&p_hB,   g_hB);
    cudaGetSymbolAddress((void**)&p_alv,  g_alv);
    cudaGetSymbolAddress((void**)&p_arv,  g_arv);
    cudaGetSymbolAddress((void**)&p_wev,  g_wev);
    cudaGetSymbolAddress((void**)&p_AT,   g_AT);

    dim3 tgrid(MPAD / 32, 4), tblk(32, 8);

    const float* hin = x0;
    float* houts[4] = {p_hA, p_hB, p_hA, (float*)d_out};
    int Dl[4] = {128, 128, 128, 256};

    for (int L = 0; L < 4; L++) {
        int D = Dl[L];
        // launch order (L==0) puts the big feat GEMM at global launch index 5 for ncu
        transpose_kernel<<<tgrid, tblk>>>(hin, p_AT, NN);
        contract_kernel<<<2, 256>>>(W[L], al[L], ar[L], p_alv, p_arv, 128, D);
        if (L == 0) {
            contract_kernel<<<1, 256>>>(We1, ae1, nullptr, p_wev, nullptr, 64, 128);
            eedge_kernel<<<(EE * 32 + 255) / 256, 256>>>(ef);
        }
        dim3 g2((MPAD + 127) / 128, D / 64);
        sgemm_tc<<<g2, 256>>>(p_AT, res[L], p_res, NN, D);
        dim3 g1((MPAD + 127) / 128, (4 * D) / 64);
        sgemm_tc<<<g1, 256>>>(p_AT, W[L], p_feat, NN, 4 * D);
        eler_kernel<<<(NN * 4 + 255) / 256, 256>>>(hin);
        if (L == 0) {
            zero_cur<<<(NN + 255) / 256, 256>>>();
            count_kernel<<<(EE + 255) / 256, 256>>>(dst);
            scan_kernel<<<1, 1024>>>();
            scatter_kernel<<<(EE + 255) / 256, 256>>>(src, dst);
        }
        alpha_kernel<<<(NN * 32 + 255) / 256, 256>>>(L == 0 ? 1 : 0);
        if (D == 128) agg_kernel<128><<<NN, 128>>>(p_feat, p_res, houts[L]);
        else          agg_kernel<256><<<NN, 256>>>(p_feat, p_res, houts[L]);
        hin = houts[L];
    }
}

// round 3
// speedup vs baseline: 1.4140x; 1.2862x over previous
#include <cuda_runtime.h>
#include <math.h>

#define NN 10000
#define EE 160000
#define HH 4
#define MPAD 10112   // 79 * 128

// ---------------- static scratch ----------------
__device__ float g_C   [NN * 1344];    // [N, NCAT] fused GEMM output (feat|res|el|er)
__device__ float g_Bcat[128 * 1344];   // [128, NCAT] fused weights
__device__ float g_hA  [NN * 128];
__device__ float g_hB  [NN * 128];
__device__ float g_AT  [128 * MPAD];
__device__ float g_inv [NN * HH];
__device__ float g_alpha[EE * HH];
__device__ float g_eedge[EE * HH];
__device__ int   g_off [NN + 1];
__device__ int   g_cur [NN];
__device__ int   g_csrc[EE];
__device__ int   g_ceid[EE];
__device__ float g_wev [64 * HH];

// ---------------- packed f32x2 FMA ----------------
__device__ __forceinline__ void ffma2(float2& c, float a, float2 b) {
    float2 a2 = make_float2(a, a);
    unsigned long long aa = *reinterpret_cast<unsigned long long*>(&a2);
    unsigned long long bb = *reinterpret_cast<unsigned long long*>(&b);
    unsigned long long cc = *reinterpret_cast<unsigned long long*>(&c);
    asm("fma.rn.f32x2 %0, %1, %2, %0;" : "+l"(cc) : "l"(aa), "l"(bb));
    c = *reinterpret_cast<float2*>(&cc);
}
__device__ __forceinline__ unsigned smem_u32(const void* p) {
    return (unsigned)__cvta_generic_to_shared(p);
}
__device__ __forceinline__ void cpa16(unsigned s, const float* g) {
    asm volatile("cp.async.cg.shared.global [%0], [%1], 16;" :: "r"(s), "l"(g));
}

// ---------------- transpose x[M,128] -> AT[128,MPAD] (zero padded) ----------
__global__ void transpose_kernel(const float* __restrict__ x, float* __restrict__ AT, int M) {
    __shared__ float t[32][33];
    int mBase = blockIdx.x * 32;
    int kBase = blockIdx.y * 32;
    int lx = threadIdx.x, ly = threadIdx.y;
#pragma unroll
    for (int j = 0; j < 32; j += 8) {
        int m = mBase + ly + j;
        t[ly + j][lx] = (m < M) ? x[(size_t)m * 128 + kBase + lx] : 0.f;
    }
    __syncthreads();
#pragma unroll
    for (int j = 0; j < 32; j += 8)
        AT[(size_t)(kBase + ly + j) * MPAD + mBase + lx] = t[lx][ly + j];
}

// ---------------- build Bcat = [W | res | (alv arv by contract) | 0pad] -----
__global__ void bcat_kernel(const float* __restrict__ W, const float* __restrict__ res,
                            float* __restrict__ Bcat, int D, int NCAT) {
    int t = blockIdx.x * blockDim.x + threadIdx.x;
    if (t >= 128 * NCAT) return;
    int i = t / NCAT, c = t - i * NCAT;
    if (c < 4 * D)            Bcat[t] = W[(size_t)i * 4 * D + c];
    else if (c < 5 * D)       Bcat[t] = res[(size_t)i * D + (c - 4 * D)];
    else if (c >= 5 * D + 8)  Bcat[t] = 0.f;
    // cols [5D, 5D+8) written by contract_kernel
}

// ---------------- contract W[128,H,D] with al/ar -> Bcat cols 5D..5D+8 ------
__global__ void contract_kernel(const float* __restrict__ W,
                                const float* __restrict__ vl, const float* __restrict__ vr,
                                float* __restrict__ Bcat, int D, int NCAT) {
    int t = blockIdx.x * blockDim.x + threadIdx.x;
    if (t >= 128 * HH) return;
    int i = t >> 2, h = t & 3;
    const float* wr = W + (size_t)(i * HH + h) * D;
    const float* al = vl + h * D;
    const float* ar = vr + h * D;
    float sl = 0.f, sr = 0.f;
    for (int d = 0; d < D; d++) {
        float w = wr[d];
        sl = fmaf(w, al[d], sl);
        sr = fmaf(w, ar[d], sr);
    }
    Bcat[(size_t)i * NCAT + 5 * D + h]     = sl;
    Bcat[(size_t)i * NCAT + 5 * D + 4 + h] = sr;
}

// ---------------- contract We1[64,H,128] with ae1 -> wev[64][H] --------------
__global__ void contract_we(const float* __restrict__ We, const float* __restrict__ ae) {
    int t = blockIdx.x * blockDim.x + threadIdx.x;
    if (t >= 64 * HH) return;
    int i = t >> 2, h = t & 3;
    const float* wr = We + (size_t)(i * HH + h) * 128;
    const float* a  = ae + h * 128;
    float s = 0.f;
    for (int d = 0; d < 128; d++) s = fmaf(wr[d], a[d], s);
    g_wev[t] = s;
}

// ---------------- SGEMM: C[M,Nc] = AT^T[M,128] @ B[128,Nc] -------------------
// BM=128, BN=64, BK=16, 256 threads, 8x4 tile, f32x2, cp.async double buffer.
__global__ void __launch_bounds__(256) sgemm_tc(const float* __restrict__ AT,
                                                const float* __restrict__ B,
                                                float* __restrict__ C, int M, int Nc) {
    __shared__ float As[2][16][128];
    __shared__ float Bs[2][16][64];
    int tid = threadIdx.x;
    int tx = tid & 15, ty = tid >> 4;
    int rowBase = blockIdx.x * 128;
    int colBase = blockIdx.y * 64;

    float2 acc[8][2];
#pragma unroll
    for (int i = 0; i < 8; i++) { acc[i][0] = make_float2(0.f, 0.f); acc[i][1] = make_float2(0.f, 0.f); }

    int ka0 = tid >> 5,         ma0 = (tid & 31) * 4;
    int ka1 = (tid + 256) >> 5, ma1 = ((tid + 256) & 31) * 4;
    int kb_ = tid >> 4,         nb_ = (tid & 15) * 4;

    cpa16(smem_u32(&As[0][ka0][ma0]), AT + (size_t)ka0 * MPAD + rowBase + ma0);
    cpa16(smem_u32(&As[0][ka1][ma1]), AT + (size_t)ka1 * MPAD + rowBase + ma1);
    cpa16(smem_u32(&Bs[0][kb_][nb_]), B + (size_t)kb_ * Nc + colBase + nb_);
    asm volatile("cp.async.commit_group;" ::: "memory");

    for (int kb = 0; kb < 8; kb++) {
        int cur = kb & 1;
        asm volatile("cp.async.wait_group 0;" ::: "memory");
        __syncthreads();
        if (kb < 7) {
            int k0 = (kb + 1) * 16;
            cpa16(smem_u32(&As[cur ^ 1][ka0][ma0]), AT + (size_t)(k0 + ka0) * MPAD + rowBase + ma0);
            cpa16(smem_u32(&As[cur ^ 1][ka1][ma1]), AT + (size_t)(k0 + ka1) * MPAD + rowBase + ma1);
            cpa16(smem_u32(&Bs[cur ^ 1][kb_][nb_]), B + (size_t)(k0 + kb_) * Nc + colBase + nb_);
            asm volatile("cp.async.commit_group;" ::: "memory");
        }
#pragma unroll
        for (int k = 0; k < 16; k++) {
            float4 a0 = *(const float4*)&As[cur][k][ty * 8];
            float4 a1 = *(const float4*)&As[cur][k][ty * 8 + 4];
            float4 b  = *(const float4*)&Bs[cur][k][tx * 4];
            float2 b01 = make_float2(b.x, b.y);
            float2 b23 = make_float2(b.z, b.w);
            ffma2(acc[0][0], a0.x, b01); ffma2(acc[0][1], a0.x, b23);
            ffma2(acc[1][0], a0.y, b01); ffma2(acc[1][1], a0.y, b23);
            ffma2(acc[2][0], a0.z, b01); ffma2(acc[2][1], a0.z, b23);
            ffma2(acc[3][0], a0.w, b01); ffma2(acc[3][1], a0.w, b23);
            ffma2(acc[4][0], a1.x, b01); ffma2(acc[4][1], a1.x, b23);
            ffma2(acc[5][0], a1.y, b01); ffma2(acc[5][1], a1.y, b23);
            ffma2(acc[6][0], a1.z, b01); ffma2(acc[6][1], a1.z, b23);
            ffma2(acc[7][0], a1.w, b01); ffma2(acc[7][1], a1.w, b23);
        }
    }
#pragma unroll
    for (int i = 0; i < 8; i++) {
        int row = rowBase + ty * 8 + i;
        if (row < M) {
            float4 o = make_float4(acc[i][0].x, acc[i][0].y, acc[i][1].x, acc[i][1].y);
            *(float4*)(C + (size_t)row * Nc + colBase + tx * 4) = o;
        }
    }
}

// ---------------- edge logit term: smem-tiled, DRAM-bound --------------------
__global__ void __launch_bounds__(256) eedge_kernel(const float* __restrict__ ef) {
    __shared__ float sf[64][68];
    __shared__ float sw[64 * HH];
    int tid = threadIdx.x;
    int e0 = blockIdx.x * 64;
    sw[tid] = g_wev[tid];            // 256 = 64*4 exactly
#pragma unroll
    for (int j = 0; j < 4; j++) {
        int idx = tid + j * 256;
        int e = idx >> 4, q = idx & 15;
        float4 v = *(const float4*)(ef + (size_t)(e0 + e) * 64 + q * 4);
        *(float4*)&sf[e][q * 4] = v;
    }
    __syncthreads();
    int e = tid >> 2, h = tid & 3;
    float acc = 0.f;
#pragma unroll
    for (int d = 0; d < 64; d++)
        acc = fmaf(sf[e][d], sw[d * 4 + h], acc);
    g_eedge[(size_t)(e0 + e) * 4 + h] = acc;
}

// ---------------- CSR build ----------------
__global__ void zero_cur() {
    int i = blockIdx.x * blockDim.x + threadIdx.x;
    if (i < NN) g_cur[i] = 0;
}
__global__ void count_kernel(const int* __restrict__ dst) {
    int e = blockIdx.x * blockDim.x + threadIdx.x;
    if (e < EE) atomicAdd(&g_cur[dst[e]], 1);
}
__global__ void scan_kernel() {
    __shared__ int sh[1024];
    int t = threadIdx.x;
    int vals[10];
    int base = t * 10;
    int s = 0;
#pragma unroll
    for (int j = 0; j < 10; j++) {
        int idx = base + j;
        int v = (idx < NN) ? g_cur[idx] : 0;
        vals[j] = s;
        s += v;
    }
    sh[t] = s;
    __syncthreads();
    for (int off = 1; off < 1024; off <<= 1) {
        int v = (t >= off) ? sh[t - off] : 0;
        __syncthreads();
        sh[t] += v;
        __syncthreads();
    }
    int excl = (t > 0) ? sh[t - 1] : 0;
#pragma unroll
    for (int j = 0; j < 10; j++) {
        int idx = base + j;
        if (idx < NN) {
            int o = excl + vals[j];
            g_off[idx] = o;
            g_cur[idx] = o;
        }
    }
    if (t == 1023) g_off[NN] = sh[1023];
}
__global__ void scatter_kernel(const int* __restrict__ src, const int* __restrict__ dst) {
    int e = blockIdx.x * blockDim.x + threadIdx.x;
    if (e < EE) {
        int p = atomicAdd(&g_cur[dst[e]], 1);
        g_csrc[p] = src[e];
        g_ceid[p] = e;
    }
}

// ---------------- edge softmax: el/er read from fused C ----------------------
__global__ void alpha_kernel(const float* __restrict__ C, int D, int NCAT, int use_edge) {
    int warp = (blockIdx.x * blockDim.x + threadIdx.x) >> 5;
    int lane = threadIdx.x & 31;
    if (warp >= NN) return;
    int n = warp;
    int b = g_off[n];
    int deg4 = (g_off[n + 1] - b) * 4;
    int h = lane & 3;
    int colE = 5 * D;
    float ern = C[(size_t)n * NCAT + colE + 4 + h];

    float mx = -1e30f;
    for (int t = lane; t < deg4; t += 32) {
        int p = b + (t >> 2);
        float e = C[(size_t)g_csrc[p] * NCAT + colE + h] + ern;
        if (use_edge) e += g_eedge[(size_t)g_ceid[p] * 4 + h];
        e = e > 0.f ? e : 0.2f * e;
        mx = fmaxf(mx, e);
    }
    mx = fmaxf(mx, __shfl_xor_sync(0xffffffffu, mx, 4));
    mx = fmaxf(mx, __shfl_xor_sync(0xffffffffu, mx, 8));
    mx = fmaxf(mx, __shfl_xor_sync(0xffffffffu, mx, 16));

    float sum = 0.f;
    for (int t = lane; t < deg4; t += 32) {
        int p = b + (t >> 2);
        float e = C[(size_t)g_csrc[p] * NCAT + colE + h] + ern;
        if (use_edge) e += g_eedge[(size_t)g_ceid[p] * 4 + h];
        e = e > 0.f ? e : 0.2f * e;
        float ex = expf(e - mx);
        g_alpha[(size_t)p * 4 + h] = ex;
        sum += ex;
    }
    sum += __shfl_xor_sync(0xffffffffu, sum, 4);
    sum += __shfl_xor_sync(0xffffffffu, sum, 8);
    sum += __shfl_xor_sync(0xffffffffu, sum, 16);
    if (lane < 4) g_inv[n * 4 + h] = 1.f / (sum + 1e-9f);
}

// ---------------- aggregation: feat + res from fused C -----------------------
template <int D>
__global__ void agg_kernel(const float* __restrict__ C, float* __restrict__ out, int NCAT) {
    constexpr int DG = D / 4;
    int n = blockIdx.x;
    int tid = threadIdx.x;            // 4*DG threads
    int h = tid / DG;
    int dg = tid % DG;
    int b = g_off[n], e = g_off[n + 1];
    float4 acc = make_float4(0.f, 0.f, 0.f, 0.f);
    const float* fbase = C + h * D + dg * 4;
    for (int p = b; p < e; ++p) {
        int s = g_csrc[p];
        float a = g_alpha[(size_t)p * 4 + h];
        float4 f = *(const float4*)(fbase + (size_t)s * NCAT);
        acc.x = fmaf(a, f.x, acc.x);
        acc.y = fmaf(a, f.y, acc.y);
        acc.z = fmaf(a, f.z, acc.z);
        acc.w = fmaf(a, f.w, acc.w);
    }
    float sc = g_inv[n * 4 + h] * 0.25f;
    acc.x *= sc; acc.y *= sc; acc.z *= sc; acc.w *= sc;

    __shared__ float4 sh[4 * DG];
    sh[tid] = acc;
    __syncthreads();
    if (tid < DG) {
        float4 r0 = sh[tid], r1 = sh[DG + tid], r2 = sh[2 * DG + tid], r3 = sh[3 * DG + tid];
        float4 rr = *(const float4*)(C + (size_t)n * NCAT + 4 * D + tid * 4);
        float4 o;
        o.x = fmaxf(r0.x + r1.x + r2.x + r3.x + rr.x, 0.f);
        o.y = fmaxf(r0.y + r1.y + r2.y + r3.y + rr.y, 0.f);
        o.z = fmaxf(r0.z + r1.z + r2.z + r3.z + rr.z, 0.f);
        o.w = fmaxf(r0.w + r1.w + r2.w + r3.w + rr.w, 0.f);
        *(float4*)(out + (size_t)n * D + tid * 4) = o;
    }
}

// ---------------- host orchestration ----------------
extern "C" void kernel_launch(void* const* d_in, const int* in_sizes, int n_in,
                              void* d_out, int out_size) {
    const float* x0  = (const float*)d_in[0];
    const float* ef  = (const float*)d_in[1];
    const int*   src = (const int*)d_in[2];
    const int*   dst = (const int*)d_in[3];
    const float* W[4]   = {(const float*)d_in[4],  (const float*)d_in[10],
                           (const float*)d_in[14], (const float*)d_in[18]};
    const float* We1    = (const float*)d_in[5];
    const float* al[4]  = {(const float*)d_in[6],  (const float*)d_in[11],
                           (const float*)d_in[15], (const float*)d_in[19]};
    const float* ar[4]  = {(const float*)d_in[7],  (const float*)d_in[12],
                           (const float*)d_in[16], (const float*)d_in[20]};
    const float* ae1    = (const float*)d_in[8];
    const float* res[4] = {(const float*)d_in[9],  (const float*)d_in[13],
                           (const float*)d_in[17], (const float*)d_in[21]};

    float *p_C, *p_Bcat, *p_hA, *p_hB, *p_AT;
    cudaGetSymbolAddress((void**)&p_C,    g_C);
    cudaGetSymbolAddress((void**)&p_Bcat, g_Bcat);
    cudaGetSymbolAddress((void**)&p_hA,   g_hA);
    cudaGetSymbolAddress((void**)&p_hB,   g_hB);
    cudaGetSymbolAddress((void**)&p_AT,   g_AT);

    dim3 tgrid(MPAD / 32, 4), tblk(32, 8);

    const float* hin = x0;
    float* houts[4] = {p_hA, p_hB, p_hA, (float*)d_out};
    int Dl[4] = {128, 128, 128, 256};

    for (int L = 0; L < 4; L++) {
        int D = Dl[L];
        int NCAT = 5 * D + 64;                 // 704 or 1344, both %64==0
        transpose_kernel<<<tgrid, tblk>>>(hin, p_AT, NN);
        bcat_kernel<<<(128 * NCAT + 255) / 256, 256>>>(W[L], res[L], p_Bcat, D, NCAT);
        contract_kernel<<<2, 256>>>(W[L], al[L], ar[L], p_Bcat, D, NCAT);
        // fused GEMM: launch #3 of this stream (ncu -s 5 lands here, given 2 harness launches)
        dim3 gg((MPAD + 127) / 128, NCAT / 64);
        sgemm_tc<<<gg, 256>>>(p_AT, p_Bcat, p_C, NN, NCAT);
        if (L == 0) {
            contract_we<<<1, 256>>>(We1, ae1);
            eedge_kernel<<<EE / 64, 256>>>(ef);
            zero_cur<<<(NN + 255) / 256, 256>>>();
            count_kernel<<<(EE + 255) / 256, 256>>>(dst);
            scan_kernel<<<1, 1024>>>();
            scatter_kernel<<<(EE + 255) / 256, 256>>>(src, dst);
        }
        alpha_kernel<<<(NN * 32 + 255) / 256, 256>>>(p_C, D, NCAT, L == 0 ? 1 : 0);
        if (D == 128) agg_kernel<128><<<NN, 128>>>(p_C, houts[L], NCAT);
        else          agg_kernel<256><<<NN, 256>>>(p_C, houts[L], NCAT);
        hin = houts[L];
    }
}